// round 13
// baseline (speedup 1.0000x reference)
#include <cuda_runtime.h>
#include <cstdint>

// Embedding gather: out[i, :] = weight[indices[i], :]
// 819200 rows x 64 fp32 = 256B/row. 8 threads/row with 256-bit ops.
//
// v13 (final grid-point probe): UNROLL=2 (both V8 gather results fit in the
// 28-reg budget -> genuinely concurrent 256-bit gathers) x 512-thread blocks
// (6400 blocks; fewer launch/retire events, wider contiguous output span per
// block). Datapath identical to v12 best: 256-bit evict_last gathers,
// 256-bit evict_first streaming stores, exact division, zero predication.
//
// Roofline evidence (v5-v12: LDG.128/LDG.256/cp.async, occ 41-83%, three L2
// policies, regs 28-46): all land at 63.1-63.8us = ~335MB irreducible traffic
// (210MB writes + ~122MB unique random 256B reads + 3MB idx) at ~5.3 TB/s
// sustained mixed-stream HBM bandwidth. This is the floor for this problem.

static constexpr int UNROLL = 2;

struct V8 { uint32_t r[8]; };

__device__ __forceinline__ V8 ldg256_evict_last(const uint32_t* p) {
    V8 v;
    asm volatile("ld.global.nc.L2::evict_last.v8.b32 {%0,%1,%2,%3,%4,%5,%6,%7}, [%8];"
                 : "=r"(v.r[0]), "=r"(v.r[1]), "=r"(v.r[2]), "=r"(v.r[3]),
                   "=r"(v.r[4]), "=r"(v.r[5]), "=r"(v.r[6]), "=r"(v.r[7])
                 : "l"(p));
    return v;
}

__device__ __forceinline__ void stg256_evict_first(uint32_t* p, const V8& v) {
    asm volatile("st.global.L2::evict_first.v8.b32 [%0], {%1,%2,%3,%4,%5,%6,%7,%8};"
                 :: "l"(p),
                    "r"(v.r[0]), "r"(v.r[1]), "r"(v.r[2]), "r"(v.r[3]),
                    "r"(v.r[4]), "r"(v.r[5]), "r"(v.r[6]), "r"(v.r[7]));
}

// Exact path: total 32B-segments divisible by blockDim*UNROLL.
__global__ __launch_bounds__(512)
void embed_gather_exact(const int* __restrict__ indices,
                        const uint32_t* __restrict__ weight,
                        uint32_t* __restrict__ out)
{
    const long long stride = (long long)gridDim.x * blockDim.x;   // mult of 8
    const long long base   = (long long)blockIdx.x * blockDim.x + threadIdx.x;
    const int       seg    = (int)(base & 7);     // 32B segment within row

    const unsigned row0       = (unsigned)(base >> 3);
    const unsigned row_stride = (unsigned)(stride >> 3);

    // Batch 1: independent index loads (warp-broadcast L1 hits)
    int idx[UNROLL];
#pragma unroll
    for (int k = 0; k < UNROLL; k++)
        idx[k] = __ldg(indices + row0 + k * row_stride);

    // Batch 2: two genuinely concurrent 256-bit gathers per thread
    V8 v[UNROLL];
#pragma unroll
    for (int k = 0; k < UNROLL; k++)
        v[k] = ldg256_evict_last(weight + (long long)idx[k] * 64 + seg * 8);

    // Batch 3: 256-bit streaming stores, evict-first (output never re-read)
#pragma unroll
    for (int k = 0; k < UNROLL; k++)
        stg256_evict_first(out + (base + (long long)k * stride) * 8, v[k]);
}

// General fallback: 128-bit, predicated, no hints (any shape).
__global__ __launch_bounds__(512)
void embed_gather_general(const int* __restrict__ indices,
                          const float4* __restrict__ weight,
                          float4* __restrict__ out,
                          long long total_vec)   // float4 count
{
    const long long stride = (long long)gridDim.x * blockDim.x;
    const long long base   = (long long)blockIdx.x * blockDim.x + threadIdx.x;

    for (long long p = base; p < total_vec; p += stride) {
        int idx = __ldg(indices + (p >> 4));
        float4 v = __ldg(weight + (long long)idx * 16 + (p & 15));
        __stcs(out + p, v);
    }
}

extern "C" void kernel_launch(void* const* d_in, const int* in_sizes, int n_in,
                              void* d_out, int out_size)
{
    const int* indices  = (const int*)d_in[0];     // 819200 int32
    long long  num_rows = in_sizes[0];

    const int threads = 512;
    long long total_vec256 = num_rows * 8;                  // 6,553,600
    long long per_block    = (long long)threads * UNROLL;   // 1024

    if (total_vec256 % per_block == 0) {
        int blocks = (int)(total_vec256 / per_block);       // 6400
        embed_gather_exact<<<blocks, threads>>>(
            indices, (const uint32_t*)d_in[1], (uint32_t*)d_out);
    } else {
        long long total_vec = num_rows * 16;
        int blocks = (int)((total_vec + per_block - 1) / per_block);
        embed_gather_general<<<blocks, threads>>>(
            indices, (const float4*)d_in[1], (float4*)d_out, total_vec);
    }
}

// round 14
// speedup vs baseline: 1.0123x; 1.0123x over previous
#include <cuda_runtime.h>
#include <cstdint>

// Embedding gather: out[i, :] = weight[indices[i], :]
// 819200 rows x 64 fp32 = 256B/row. 8 threads/row with 256-bit ops.
//
// FINAL (= v12, the measured best at 63.10us): UNROLL=2 x 256-thread blocks,
// 12800 blocks, 28 regs, occ ~81%. Both V8 gather results fit in registers ->
// two genuinely concurrent 256-bit gathers per thread at max occupancy.
// 256-bit evict_last gathers (table biased to stay in L2), 256-bit
// evict_first streaming stores (output never re-read), exact division,
// zero predication.
//
// Roofline evidence (v5-v13: LDG.128/LDG.256/cp.async, occ 41-83%, three L2
// policies, regs 28-46): all land at 63.1-63.8us = ~335MB irreducible traffic
// (210MB mandatory fp32 writes + ~122MB unique random 256B reads + 3MB idx)
// at ~5.3 TB/s sustained mixed random-read/streaming-write HBM bandwidth.
// This configuration is the measured floor for this problem.

static constexpr int UNROLL = 2;

struct V8 { uint32_t r[8]; };

__device__ __forceinline__ V8 ldg256_evict_last(const uint32_t* p) {
    V8 v;
    asm volatile("ld.global.nc.L2::evict_last.v8.b32 {%0,%1,%2,%3,%4,%5,%6,%7}, [%8];"
                 : "=r"(v.r[0]), "=r"(v.r[1]), "=r"(v.r[2]), "=r"(v.r[3]),
                   "=r"(v.r[4]), "=r"(v.r[5]), "=r"(v.r[6]), "=r"(v.r[7])
                 : "l"(p));
    return v;
}

__device__ __forceinline__ void stg256_evict_first(uint32_t* p, const V8& v) {
    asm volatile("st.global.L2::evict_first.v8.b32 [%0], {%1,%2,%3,%4,%5,%6,%7,%8};"
                 :: "l"(p),
                    "r"(v.r[0]), "r"(v.r[1]), "r"(v.r[2]), "r"(v.r[3]),
                    "r"(v.r[4]), "r"(v.r[5]), "r"(v.r[6]), "r"(v.r[7]));
}

// Exact path: total 32B-segments divisible by blockDim*UNROLL.
__global__ __launch_bounds__(256)
void embed_gather_exact(const int* __restrict__ indices,
                        const uint32_t* __restrict__ weight,
                        uint32_t* __restrict__ out)
{
    const long long stride = (long long)gridDim.x * blockDim.x;   // mult of 8
    const long long base   = (long long)blockIdx.x * blockDim.x + threadIdx.x;
    const int       seg    = (int)(base & 7);     // 32B segment within row

    const unsigned row0       = (unsigned)(base >> 3);
    const unsigned row_stride = (unsigned)(stride >> 3);

    // Batch 1: independent index loads (warp-broadcast L1 hits)
    int idx[UNROLL];
#pragma unroll
    for (int k = 0; k < UNROLL; k++)
        idx[k] = __ldg(indices + row0 + k * row_stride);

    // Batch 2: two genuinely concurrent 256-bit gathers per thread
    V8 v[UNROLL];
#pragma unroll
    for (int k = 0; k < UNROLL; k++)
        v[k] = ldg256_evict_last(weight + (long long)idx[k] * 64 + seg * 8);

    // Batch 3: 256-bit streaming stores, evict-first (output never re-read)
#pragma unroll
    for (int k = 0; k < UNROLL; k++)
        stg256_evict_first(out + (base + (long long)k * stride) * 8, v[k]);
}

// General fallback: 128-bit, predicated, no hints (any shape).
__global__ __launch_bounds__(256)
void embed_gather_general(const int* __restrict__ indices,
                          const float4* __restrict__ weight,
                          float4* __restrict__ out,
                          long long total_vec)   // float4 count
{
    const long long stride = (long long)gridDim.x * blockDim.x;
    const long long base   = (long long)blockIdx.x * blockDim.x + threadIdx.x;

    for (long long p = base; p < total_vec; p += stride) {
        int idx = __ldg(indices + (p >> 4));
        float4 v = __ldg(weight + (long long)idx * 16 + (p & 15));
        __stcs(out + p, v);
    }
}

extern "C" void kernel_launch(void* const* d_in, const int* in_sizes, int n_in,
                              void* d_out, int out_size)
{
    const int* indices  = (const int*)d_in[0];     // 819200 int32
    long long  num_rows = in_sizes[0];

    const int threads = 256;
    long long total_vec256 = num_rows * 8;                  // 6,553,600
    long long per_block    = (long long)threads * UNROLL;   // 512

    if (total_vec256 % per_block == 0) {
        int blocks = (int)(total_vec256 / per_block);       // 12800
        embed_gather_exact<<<blocks, threads>>>(
            indices, (const uint32_t*)d_in[1], (uint32_t*)d_out);
    } else {
        long long total_vec = num_rows * 16;
        int blocks = (int)((total_vec + per_block - 1) / per_block);
        embed_gather_general<<<blocks, threads>>>(
            indices, (const float4*)d_in[1], (float4*)d_out, total_vec);
    }
}